// round 13
// baseline (speedup 1.0000x reference)
#include <cuda_runtime.h>

// SingleChannelInterpolation — fused softmax interpolation with d-sorted
// far-field culling. B=32, C=128, W=128, H=128, KAPPA=10.
// Outputs: y [B,C,H] | w [B,C,H] | y_trans [B,C,H].
//
// log2 domain: s2 = ll - a2*(d-t)^2, ll = log2(m), a2 = softplus(kernel)*log2e.
// Shift: Mg = max_w(-a2*(d-t)^2) (exact, ll-free; valid since ll <= 0; slack
//   <= 10 so S >= 2^-10). Transient: sMt = 10*sM - 9*ll exactly, sMt <= 0.
// Culling: terms with sM < -35 contribute < 2^-18 relative. Observations are
//   RANK-SORTED by d (u64 key = float bits || index: exact, deterministic,
//   tie-free). Sorted, the kept pairs for each (warp, j) form a contiguous
//   interval: one ballot finds [kstart, kstart+kcnt), and pass 2 runs a plain
//   counted loop — no per-body tests. Window half-width thr_j =
//   sqrt((35 + Qj)/alpha_min), Qj = max_lane(-Mg): outside it, for every lane
//   a2*(d-t)^2 >= alpha_min*thr^2 = 35 + Qj >= 35 - Mg  ->  sM < -35. The
//   argmax pair is always inside (q* <= Qj/a2 <= thr^2) so S > 0.
// Softmax sums are permutation-invariant -> sorting is transparent.

constexpr int B = 32, C = 128, W = 128, H = 128;
constexpr int BDIM = 128;          // 4 warps
constexpr int CH = 2;              // channels per block; warp = (ch, w-half)
constexpr int W2 = W / 2;          // 64 pairs
constexpr int HALFP = W2 / 2;      // 32 pairs per warp
constexpr int JN = 4;              // h-groups per warp
constexpr float LOG2E = 1.4426950408889634f;
constexpr float LN2   = 0.6931471805599453f;
constexpr float SKIP_THR = 35.0f;  // rel contribution cutoff 2^-35 (S >= 2^-10)

typedef unsigned long long u64;

__device__ __forceinline__ float ex2(float x) {
    float y; asm("ex2.approx.ftz.f32 %0, %1;" : "=f"(y) : "f"(x)); return y;
}
__device__ __forceinline__ float lg2(float x) {
    float y; asm("lg2.approx.ftz.f32 %0, %1;" : "=f"(y) : "f"(x)); return y;
}
__device__ __forceinline__ u64 pk(float lo, float hi) {
    u64 r; asm("mov.b64 %0, {%1, %2};" : "=l"(r) : "f"(lo), "f"(hi)); return r;
}
__device__ __forceinline__ void unpk(u64 v, float& lo, float& hi) {
    asm("mov.b64 {%0, %1}, %2;" : "=f"(lo), "=f"(hi) : "l"(v));
}
__device__ __forceinline__ u64 add2(u64 a, u64 b) {
    u64 r; asm("add.rn.f32x2 %0, %1, %2;" : "=l"(r) : "l"(a), "l"(b)); return r;
}
__device__ __forceinline__ u64 mul2(u64 a, u64 b) {
    u64 r; asm("mul.rn.f32x2 %0, %1, %2;" : "=l"(r) : "l"(a), "l"(b)); return r;
}
__device__ __forceinline__ u64 fma2(u64 a, u64 b, u64 c) {
    u64 r; asm("fma.rn.f32x2 %0, %1, %2, %3;" : "=l"(r) : "l"(a), "l"(b), "l"(c)); return r;
}

__global__ __launch_bounds__(BDIM)
void interp_kernel(const float* __restrict__ x_t,
                   const float* __restrict__ d_in_,
                   const float* __restrict__ m_in,
                   const float* __restrict__ kern,
                   float* __restrict__ out)
{
    __shared__ float4 DN[CH][W2];      // sorted (d0, d1, na0, na1), na = -alpha2
    __shared__ float4 LX[CH][W2];      // sorted (ll0, ll1, x0, x1)
    __shared__ u64    DSK[CH][W];      // sort keys (float bits << 32 | index)
    __shared__ float  MSH[CH][2][H];   // per-half max exchange
    __shared__ float4 ACC[CH][H];      // half-1 partials (S, Y, St, Yt)
    __shared__ float  WMAXNA[4];       // per-warp max(na) for alpha_min

    const int tid = threadIdx.x;
    const int bc0 = blockIdx.x * CH;

    // ---- Phase A: load raw values, build sort keys
    float myd[CH], myll[CH], myx[CH];
    float myna = -log1pf(expf(kern[tid])) * LOG2E;   // na = -alpha2
    #pragma unroll
    for (int c = 0; c < CH; c++) {
        int g = (bc0 + c) * W + tid;
        myd[c]  = d_in_[g];
        myll[c] = lg2(m_in[g]);
        myx[c]  = x_t[g];
        DSK[c][tid] = ((u64)__float_as_uint(myd[c]) << 32) | (unsigned)tid;
    }
    // alpha_min = -max(na) over the 128 kernel values
    {
        float wna = myna;
        #pragma unroll
        for (int s = 16; s > 0; s >>= 1)
            wna = fmaxf(wna, __shfl_xor_sync(0xffffffffu, wna, s));
        if ((tid & 31) == 0) WMAXNA[tid >> 5] = wna;
    }
    __syncthreads();

    // ---- Phase B: exact rank (d>=0 so float bits are order-isomorphic),
    // scatter into sorted pair layout. Broadcast LDS (all lanes same chunk).
    #pragma unroll
    for (int c = 0; c < CH; c++) {
        u64 mykey = DSK[c][tid];
        int rank = 0;
        const ulonglong2* ks = (const ulonglong2*)DSK[c];
        #pragma unroll 8
        for (int q = 0; q < W / 2; q++) {
            ulonglong2 kk = ks[q];
            rank += (kk.x < mykey) + (kk.y < mykey);
        }
        int pr = rank >> 1, sl = rank & 1;
        ((float*)&DN[c][pr])[sl]     = myd[c];
        ((float*)&DN[c][pr])[2 + sl] = myna;
        ((float*)&LX[c][pr])[sl]     = myll[c];
        ((float*)&LX[c][pr])[2 + sl] = myx[c];
    }
    __syncthreads();

    const float amax_na = fmaxf(fmaxf(WMAXNA[0], WMAXNA[1]),
                                fmaxf(WMAXNA[2], WMAXNA[3]));
    const float alpha_min = -amax_na;

    const int warp = tid >> 5;
    const int lane = tid & 31;
    const int ch   = warp >> 1;
    const int half = warp & 1;
    const int k0   = half * HALFP;
    const ulonglong2* __restrict__ dn2 = (const ulonglong2*)DN[ch];
    const ulonglong2* __restrict__ lx2 = (const ulonglong2*)LX[ch];

    // per-lane h targets: h = lane + 32*j, t = h * 128/127 (linspace(0,128,128))
    u64 nt2[JN];
    float Ma[JN], Mb[JN];
    #pragma unroll
    for (int j = 0; j < JN; j++) {
        float t = (float)(lane + 32 * j) * (128.0f / 127.0f);
        nt2[j] = pk(-t, -t);
        Ma[j] = -1e30f; Mb[j] = -1e30f;
    }

    // ---- Pass 1 (own half, full scan): Mg[j] = max_w(-a2*(d-t)^2)
    #pragma unroll 4
    for (int k = k0; k < k0 + HALFP; k++) {
        ulonglong2 dn = dn2[k];
        #pragma unroll
        for (int j = 0; j < JN; j++) {
            u64 diff = add2(dn.x, nt2[j]);
            u64 v    = mul2(diff, diff);
            u64 nq   = mul2(dn.y, v);
            float a, b; unpk(nq, a, b);
            Ma[j] = fmaxf(Ma[j], a);
            Mb[j] = fmaxf(Mb[j], b);
        }
    }
    #pragma unroll
    for (int j = 0; j < JN; j++)
        MSH[ch][half][32 * j + lane] = fmaxf(Ma[j], Mb[j]);
    __syncthreads();

    float Mg[JN];
    u64 nM2[JN];
    int kstart[JN], kcnt[JN];
    #pragma unroll
    for (int j = 0; j < JN; j++) {
        Mg[j] = fmaxf(MSH[ch][half][32 * j + lane],
                      MSH[ch][half ^ 1][32 * j + lane]);
        nM2[j] = pk(-Mg[j], -Mg[j]);
        // window: thr_j from worst lane in group; ballot over own-half pairs
        float Q = -Mg[j];
        #pragma unroll
        for (int s = 16; s > 0; s >>= 1)
            Q = fmaxf(Q, __shfl_xor_sync(0xffffffffu, Q, s));
        float thr = sqrtf(__fdividef(SKIP_THR + Q, alpha_min));
        float tmin = (float)(32 * j) * (128.0f / 127.0f);
        float tmax = (float)(32 * j + 31) * (128.0f / 127.0f);
        float lo = tmin - thr, hi = tmax + thr;
        float2 dp = *(const float2*)&DN[ch][k0 + lane];   // d0 <= d1 (sorted)
        bool keep = (dp.x <= hi) && (dp.y >= lo);
        unsigned mask = __ballot_sync(0xffffffffu, keep); // contiguous run
        kcnt[j]   = __popc(mask);
        kstart[j] = k0 + (mask ? (__ffs(mask) - 1) : 0);
    }

    const u64 ten2 = pk(10.0f, 10.0f);
    const u64 n9   = pk(-9.0f, -9.0f);

    // ---- Pass 2: only windowed pairs; both softmax sums
    float S[JN]  = {0,0,0,0}, Y[JN]  = {0,0,0,0};
    float St[JN] = {0,0,0,0}, Yt[JN] = {0,0,0,0};
    #pragma unroll
    for (int j = 0; j < JN; j++) {
        u64 ntj = nt2[j], nMj = nM2[j];
        int ks = kstart[j], n = kcnt[j];
        #pragma unroll 2
        for (int i = 0; i < n; i++) {
            int k = ks + i;
            ulonglong2 dn = dn2[k];
            ulonglong2 lx = lx2[k];
            u64 diff = add2(dn.x, ntj);
            u64 v    = mul2(diff, diff);
            u64 s2   = fma2(dn.y, v, lx.x);     // ll - a2*(d-t)^2
            u64 sM   = add2(s2, nMj);           // s2 - Mg <= 0
            u64 rr   = mul2(n9, lx.x);          // -9*ll
            u64 sMt  = fma2(ten2, sM, rr);      // 10*sM - 9*ll <= 0
            float a, b; unpk(sM,  a, b);
            float c, e; unpk(sMt, c, e);
            float e0 = ex2(a), e1 = ex2(b);
            float f0 = ex2(c), f1 = ex2(e);
            float x0, x1; unpk(lx.y, x0, x1);
            S[j]  += e0;                  S[j]  += e1;
            Y[j]   = fmaf(e0, x0, Y[j]);  Y[j]   = fmaf(e1, x1, Y[j]);
            St[j] += f0;                  St[j] += f1;
            Yt[j]  = fmaf(f0, x0, Yt[j]); Yt[j]  = fmaf(f1, x1, Yt[j]);
        }
    }

    // ---- Combine halves + epilogue (half 0 writes)
    if (half == 1) {
        #pragma unroll
        for (int j = 0; j < JN; j++)
            ACC[ch][32 * j + lane] = make_float4(S[j], Y[j], St[j], Yt[j]);
    }
    __syncthreads();
    if (half == 0) {
        const int bc = bc0 + ch;
        #pragma unroll
        for (int j = 0; j < JN; j++) {
            float4 o = ACC[ch][32 * j + lane];
            float Sg  = S[j]  + o.x;
            float Yg  = Y[j]  + o.y;
            float Stg = St[j] + o.z;
            float Ytg = Yt[j] + o.w;
            int h = lane + 32 * j;
            int q = bc * H + h;
            out[q]             = __fdividef(Yg, Sg);
            out[B*C*H + q]     = LN2 * (Mg[j] + lg2(Sg));
            out[2*B*C*H + q]   = __fdividef(Ytg, Stg);
        }
    }
}

extern "C" void kernel_launch(void* const* d_in, const int* in_sizes, int n_in,
                              void* d_out, int out_size)
{
    const float* x_t  = (const float*)d_in[0];
    const float* d    = (const float*)d_in[1];
    const float* m    = (const float*)d_in[2];
    const float* kern = (const float*)d_in[3];
    float* out = (float*)d_out;

    interp_kernel<<<(B * C) / CH, BDIM>>>(x_t, d, m, kern, out);
}

// round 15
// speedup vs baseline: 1.1145x; 1.1145x over previous
#include <cuda_runtime.h>

// SingleChannelInterpolation — fused softmax interpolation with unsorted
// ballot-mask far-field culling. B=32, C=128, W=128, H=128, KAPPA=10.
// Outputs: y [B,C,H] | w [B,C,H] | y_trans [B,C,H].
//
// log2 domain: s2 = ll - a2*(d-t)^2, ll = log2(m), a2 = softplus(kernel)*log2e.
// Shift: Mg = max_w(-a2*(d-t)^2) (ll-free; valid since ll <= 0, slack <= 10
//   -> S >= 2^-10). Transient: sMt = 10*sM - 9*ll exactly (<= 90, f32-safe).
// Culling: pair w excluded only if every element is outside
//   [tmin-thr, tmax+thr], thr^2 = (35+Q)/alpha_min, Q = warp-max(-Mg).
//   Then for every lane: a2*(d-t)^2 > 35 + Q >= 35 - Mg -> sM < -35 ->
//   rel contribution < 2^-25. Each lane's argmax pair is provably inside
//   (dist^2 <= Q/alpha_min < thr^2) -> S > 0 always.
// Structure: 1 channel/block (4 warps), warp j owns h = 32j+lane. Keep set
//   built once as two 32-bit ballot masks over the 64 unsorted w-pairs;
//   pass 2 iterates set bits (no sort, no skipped-iteration cost).

constexpr int B = 32, C = 128, W = 128, H = 128;
constexpr int BDIM = 128;          // 4 warps, 1 channel per block
constexpr int W2 = W / 2;          // 64 pairs
constexpr float LOG2E = 1.4426950408889634f;
constexpr float LN2   = 0.6931471805599453f;
constexpr float TSCL  = 128.0f / 127.0f;   // linspace(0,128,128) step
constexpr float SKIP_THR = 35.0f;

typedef unsigned long long u64;

__device__ __forceinline__ float ex2(float x) {
    float y; asm("ex2.approx.ftz.f32 %0, %1;" : "=f"(y) : "f"(x)); return y;
}
__device__ __forceinline__ float lg2(float x) {
    float y; asm("lg2.approx.ftz.f32 %0, %1;" : "=f"(y) : "f"(x)); return y;
}
__device__ __forceinline__ u64 pk(float lo, float hi) {
    u64 r; asm("mov.b64 %0, {%1, %2};" : "=l"(r) : "f"(lo), "f"(hi)); return r;
}
__device__ __forceinline__ void unpk(u64 v, float& lo, float& hi) {
    asm("mov.b64 {%0, %1}, %2;" : "=f"(lo), "=f"(hi) : "l"(v));
}
__device__ __forceinline__ u64 add2(u64 a, u64 b) {
    u64 r; asm("add.rn.f32x2 %0, %1, %2;" : "=l"(r) : "l"(a), "l"(b)); return r;
}
__device__ __forceinline__ u64 mul2(u64 a, u64 b) {
    u64 r; asm("mul.rn.f32x2 %0, %1, %2;" : "=l"(r) : "l"(a), "l"(b)); return r;
}
__device__ __forceinline__ u64 fma2(u64 a, u64 b, u64 c) {
    u64 r; asm("fma.rn.f32x2 %0, %1, %2, %3;" : "=l"(r) : "l"(a), "l"(b), "l"(c)); return r;
}

__global__ __launch_bounds__(BDIM)
void interp_kernel(const float* __restrict__ x_t,
                   const float* __restrict__ d_in_,
                   const float* __restrict__ m_in,
                   const float* __restrict__ kern,
                   float* __restrict__ out)
{
    __shared__ float4 DN[W2];       // (d0, d1, na0, na1)   na = -alpha2
    __shared__ float4 LX[W2];       // (ll0, ll1, x0, x1)   ll = log2(m)
    __shared__ float  SRED[4];      // per-warp max(na) for alpha_min

    const int tid  = threadIdx.x;
    const int bc   = blockIdx.x;    // one (b,c) channel per block
    const int warp = tid >> 5;
    const int lane = tid & 31;

    // ---- setup: 128 threads load the channel's 128 observations
    {
        int g = bc * W + tid;
        float na = -log1pf(expf(kern[tid])) * LOG2E;
        float ll = lg2(m_in[g]);
        int pr = tid >> 1, sl = tid & 1;
        ((float*)&DN[pr])[sl]     = d_in_[g];
        ((float*)&DN[pr])[2 + sl] = na;
        ((float*)&LX[pr])[sl]     = ll;
        ((float*)&LX[pr])[2 + sl] = x_t[g];
        float wna = na;
        #pragma unroll
        for (int s = 16; s > 0; s >>= 1)
            wna = fmaxf(wna, __shfl_xor_sync(0xffffffffu, wna, s));
        if (lane == 0) SRED[warp] = wna;
    }
    __syncthreads();

    const float alpha_min = -fmaxf(fmaxf(SRED[0], SRED[1]),
                                   fmaxf(SRED[2], SRED[3]));
    const ulonglong2* __restrict__ dn2 = (const ulonglong2*)DN;
    const ulonglong2* __restrict__ lx2 = (const ulonglong2*)LX;

    // per-lane h target: h = 32*warp + lane, t = h * 128/127
    const int h   = 32 * warp + lane;
    const float t = (float)h * TSCL;
    const u64 ntp = pk(-t, -t);

    // ---- Pass 1: Mg = max_w(-a2*(d-t)^2) over all 64 pairs
    float Ma = -1e30f, Mb = -1e30f;
    #pragma unroll 4
    for (int k = 0; k < W2; k++) {
        ulonglong2 dn = dn2[k];
        u64 diff = add2(dn.x, ntp);
        u64 v    = mul2(diff, diff);
        u64 nq   = mul2(dn.y, v);
        float a, b; unpk(nq, a, b);
        Ma = fmaxf(Ma, a);
        Mb = fmaxf(Mb, b);
    }
    const float Mg = fmaxf(Ma, Mb);
    const u64 nMp = pk(-Mg, -Mg);

    // ---- Window: warp-uniform [lo, hi]
    float Q = -Mg;
    #pragma unroll
    for (int s = 16; s > 0; s >>= 1)
        Q = fmaxf(Q, __shfl_xor_sync(0xffffffffu, Q, s));
    const float thr  = sqrtf(__fdividef(SKIP_THR + Q, alpha_min));
    const float tmin = (float)(32 * warp) * TSCL;
    const float tmax = (float)(32 * warp + 31) * TSCL;
    const float lo = tmin - thr, hi = tmax + thr;

    // ---- Keep masks: 2 ballots over the 64 pairs (keep if any elem in window)
    unsigned keep_mask[2];
    #pragma unroll
    for (int half = 0; half < 2; half++) {
        float2 dp = *(const float2*)&DN[half * 32 + lane];
        bool keep = (dp.x >= lo && dp.x <= hi) || (dp.y >= lo && dp.y <= hi);
        keep_mask[half] = __ballot_sync(0xffffffffu, keep);
    }

    const u64 ten2 = pk(10.0f, 10.0f);
    const u64 n9   = pk(-9.0f, -9.0f);

    // ---- Pass 2: windowed pairs only; packed accumulation
    u64 S2 = 0, Y2 = 0, St2 = 0, Yt2 = 0;
    #pragma unroll
    for (int half = 0; half < 2; half++) {
        unsigned msk = keep_mask[half];
        while (msk) {
            int i = __ffs(msk) - 1;
            msk &= msk - 1;
            int k = half * 32 + i;
            ulonglong2 dn = dn2[k];
            ulonglong2 lx = lx2[k];
            u64 diff = add2(dn.x, ntp);
            u64 v    = mul2(diff, diff);
            u64 s2   = fma2(dn.y, v, lx.x);     // ll - a2*(d-t)^2
            u64 sM   = add2(s2, nMp);           // s2 - Mg <= 0
            u64 rr   = mul2(n9, lx.x);          // -9*ll
            u64 sMt  = fma2(ten2, sM, rr);      // 10*sM - 9*ll
            float a, b; unpk(sM,  a, b);
            float c, e; unpk(sMt, c, e);
            u64 e2 = pk(ex2(a), ex2(b));
            u64 f2 = pk(ex2(c), ex2(e));
            S2  = add2(S2,  e2);
            Y2  = fma2(e2, lx.y, Y2);
            St2 = add2(St2, f2);
            Yt2 = fma2(f2, lx.y, Yt2);
        }
    }

    // ---- Epilogue
    float s0, s1, y0, y1, st0, st1, yt0, yt1;
    unpk(S2,  s0,  s1);
    unpk(Y2,  y0,  y1);
    unpk(St2, st0, st1);
    unpk(Yt2, yt0, yt1);
    float Sg  = s0 + s1,   Yg  = y0 + y1;
    float Stg = st0 + st1, Ytg = yt0 + yt1;
    int o = bc * H + h;
    out[o]             = __fdividef(Yg, Sg);
    out[B*C*H + o]     = LN2 * (Mg + lg2(Sg));
    out[2*B*C*H + o]   = __fdividef(Ytg, Stg);
}

extern "C" void kernel_launch(void* const* d_in, const int* in_sizes, int n_in,
                              void* d_out, int out_size)
{
    const float* x_t  = (const float*)d_in[0];
    const float* d    = (const float*)d_in[1];
    const float* m    = (const float*)d_in[2];
    const float* kern = (const float*)d_in[3];
    float* out = (float*)d_out;

    interp_kernel<<<B * C, BDIM>>>(x_t, d, m, kern, out);
}

// round 17
// speedup vs baseline: 1.2654x; 1.1354x over previous
#include <cuda_runtime.h>

// SingleChannelInterpolation — fused softmax interpolation, sqrt-folded
// pass 1 + half-warp subwindow culling. B=32, C=128, W=128, H=128, KAPPA=10.
// Outputs: y [B,C,H] | w [B,C,H] | y_trans [B,C,H].
//
// log2 domain: s2 = ll - vv, vv = (sqa*(d-t))^2, sqa = sqrt(softplus(k)*log2e),
//   ll = log2(m). Pass 1 tracks min vv -> Mg = -min vv is the EXACT max of
//   -vv over the computed values (pass 2 recomputes vv identically, so
//   sM = s2 - Mg <= 0 always; ll <= 0 gives shift slack <= 10 -> S >= 2^-10).
// Transient: sMt = 10*sM - 9*ll exactly (<= 90, f32-safe both directions).
// Culling: element excluded only if vv > 35 + Q_sub for its half-warp
//   subgroup (Q_sub = subgroup-max of min vv) -> dropped terms < 2^-25 rel.
//   Window |d - tc| <= R, R = 7.5*TSCL + thr, thr^2 = (35+Q_sub)/alpha_min.
//   Each lane's argmin-vv element is provably inside -> masks nonempty.
// Masks: 4 warp-uniform ballots (2 subgroups x 2 pair-halves); pass 2
//   iterates per-lane-selected masks (SIMT cost = max of the two counts).

constexpr int B = 32, C = 128, W = 128, H = 128;
constexpr int BDIM = 128;          // 4 warps, 1 channel per block
constexpr int W2 = W / 2;          // 64 pairs
constexpr float LOG2E = 1.4426950408889634f;
constexpr float LN2   = 0.6931471805599453f;
constexpr float TSCL  = 128.0f / 127.0f;   // linspace(0,128,128) step
constexpr float SKIP_THR = 35.0f;

typedef unsigned long long u64;

__device__ __forceinline__ float ex2(float x) {
    float y; asm("ex2.approx.ftz.f32 %0, %1;" : "=f"(y) : "f"(x)); return y;
}
__device__ __forceinline__ float lg2(float x) {
    float y; asm("lg2.approx.ftz.f32 %0, %1;" : "=f"(y) : "f"(x)); return y;
}
__device__ __forceinline__ u64 pk(float lo, float hi) {
    u64 r; asm("mov.b64 %0, {%1, %2};" : "=l"(r) : "f"(lo), "f"(hi)); return r;
}
__device__ __forceinline__ void unpk(u64 v, float& lo, float& hi) {
    asm("mov.b64 {%0, %1}, %2;" : "=f"(lo), "=f"(hi) : "l"(v));
}
__device__ __forceinline__ u64 add2(u64 a, u64 b) {
    u64 r; asm("add.rn.f32x2 %0, %1, %2;" : "=l"(r) : "l"(a), "l"(b)); return r;
}
__device__ __forceinline__ u64 mul2(u64 a, u64 b) {
    u64 r; asm("mul.rn.f32x2 %0, %1, %2;" : "=l"(r) : "l"(a), "l"(b)); return r;
}
__device__ __forceinline__ u64 fma2(u64 a, u64 b, u64 c) {
    u64 r; asm("fma.rn.f32x2 %0, %1, %2, %3;" : "=l"(r) : "l"(a), "l"(b), "l"(c)); return r;
}

__global__ __launch_bounds__(BDIM)
void interp_kernel(const float* __restrict__ x_t,
                   const float* __restrict__ d_in_,
                   const float* __restrict__ m_in,
                   const float* __restrict__ kern,
                   float* __restrict__ out)
{
    __shared__ float4 DN[W2];       // (ud0, ud1, sqa0, sqa1)  ud = sqa*d
    __shared__ float4 LX[W2];       // (ll0, ll1, x0, x1)      ll = log2(m)
    __shared__ float  SRED[4];      // per-warp min(a2) for alpha_min

    const int tid  = threadIdx.x;
    const int bc   = blockIdx.x;    // one (b,c) channel per block
    const int warp = tid >> 5;
    const int lane = tid & 31;

    // ---- setup: 128 threads load the channel's 128 observations
    {
        int g = bc * W + tid;
        float a2  = log1pf(expf(kern[tid])) * LOG2E;
        float sqa = sqrtf(a2);
        float ll  = lg2(m_in[g]);
        int pr = tid >> 1, sl = tid & 1;
        ((float*)&DN[pr])[sl]     = sqa * d_in_[g];
        ((float*)&DN[pr])[2 + sl] = sqa;
        ((float*)&LX[pr])[sl]     = ll;
        ((float*)&LX[pr])[2 + sl] = x_t[g];
        float wa = a2;
        #pragma unroll
        for (int s = 16; s > 0; s >>= 1)
            wa = fminf(wa, __shfl_xor_sync(0xffffffffu, wa, s));
        if (lane == 0) SRED[warp] = wa;
    }
    __syncthreads();

    const float alpha_min = fminf(fminf(SRED[0], SRED[1]),
                                  fminf(SRED[2], SRED[3]));
    const ulonglong2* __restrict__ dn2 = (const ulonglong2*)DN;
    const ulonglong2* __restrict__ lx2 = (const ulonglong2*)LX;

    // per-lane h target: h = 32*warp + lane, t = h * 128/127
    const int h   = 32 * warp + lane;
    const float t = (float)h * TSCL;
    const u64 ntp = pk(-t, -t);

    // ---- Pass 1: minvv = min_w (sqa*(d-t))^2  (two scalar FMNMX chains)
    float mina = 1e30f, minb = 1e30f;
    #pragma unroll 4
    for (int k = 0; k < W2; k++) {
        ulonglong2 dn = dn2[k];
        u64 v  = fma2(dn.y, ntp, dn.x);   // sqa*(d - t)
        u64 vv = mul2(v, v);              // a2*(d-t)^2
        float a, b; unpk(vv, a, b);
        mina = fminf(mina, a);
        minb = fminf(minb, b);
    }
    const float minvv = fminf(mina, minb);
    const float Mg  = -minvv;
    const u64 nMp = pk(minvv, minvv);     // -Mg

    // ---- Subgroup windows (half-warp): Q_sub = subgroup-max(minvv)
    float gq = minvv;
    #pragma unroll
    for (int s = 8; s > 0; s >>= 1)
        gq = fmaxf(gq, __shfl_xor_sync(0xffffffffu, gq, s));
    // gq now = max over own 16-lane subgroup
    const float QA = __shfl_sync(0xffffffffu, gq, 0);
    const float QB = __shfl_sync(0xffffffffu, gq, 16);
    const float thrA = sqrtf(__fdividef(SKIP_THR + QA, alpha_min));
    const float thrB = sqrtf(__fdividef(SKIP_THR + QB, alpha_min));
    const float tcA = ((float)(32 * warp) + 7.5f) * TSCL;
    const float tcB = ((float)(32 * warp) + 23.5f) * TSCL;
    const float RA = 7.5f * TSCL + thrA;
    const float RB = 7.5f * TSCL + thrB;

    // ---- Keep masks: 4 warp-uniform ballots (subgroup x pair-half).
    // Element e of pair p kept iff |ud_e - sqa_e*tc| <= sqa_e*R.
    unsigned mA[2], mB[2];
    #pragma unroll
    for (int half = 0; half < 2; half++) {
        float4 dn = DN[half * 32 + lane];
        float cA0 = fmaf(-tcA, dn.z, dn.x), cA1 = fmaf(-tcA, dn.w, dn.y);
        bool kA = (fabsf(cA0) <= dn.z * RA) || (fabsf(cA1) <= dn.w * RA);
        mA[half] = __ballot_sync(0xffffffffu, kA);
        float cB0 = fmaf(-tcB, dn.z, dn.x), cB1 = fmaf(-tcB, dn.w, dn.y);
        bool kB = (fabsf(cB0) <= dn.z * RB) || (fabsf(cB1) <= dn.w * RB);
        mB[half] = __ballot_sync(0xffffffffu, kB);
    }
    const bool inA = (lane < 16);

    const u64 ten2 = pk(10.0f, 10.0f);
    const u64 n9   = pk(-9.0f, -9.0f);
    const u64 n1   = pk(-1.0f, -1.0f);

    // ---- Pass 2: windowed pairs only; packed accumulation
    u64 S2 = 0, Y2 = 0, St2 = 0, Yt2 = 0;
    #pragma unroll
    for (int half = 0; half < 2; half++) {
        unsigned msk = inA ? mA[half] : mB[half];
        while (msk) {
            int i = __ffs(msk) - 1;
            msk &= msk - 1;
            int k = half * 32 + i;
            ulonglong2 dn = dn2[k];
            ulonglong2 lx = lx2[k];
            u64 v    = fma2(dn.y, ntp, dn.x);   // sqa*(d-t)
            u64 vv   = mul2(v, v);
            u64 s2   = fma2(n1, vv, lx.x);      // ll - vv
            u64 sM   = add2(s2, nMp);           // s2 - Mg <= 0 (exact)
            u64 rr   = mul2(n9, lx.x);          // -9*ll
            u64 sMt  = fma2(ten2, sM, rr);      // 10*sM - 9*ll
            float a, b; unpk(sM,  a, b);
            float c, e; unpk(sMt, c, e);
            u64 e2 = pk(ex2(a), ex2(b));
            u64 f2 = pk(ex2(c), ex2(e));
            S2  = add2(S2,  e2);
            Y2  = fma2(e2, lx.y, Y2);
            St2 = add2(St2, f2);
            Yt2 = fma2(f2, lx.y, Yt2);
        }
    }

    // ---- Epilogue
    float s0, s1, y0, y1, st0, st1, yt0, yt1;
    unpk(S2,  s0,  s1);
    unpk(Y2,  y0,  y1);
    unpk(St2, st0, st1);
    unpk(Yt2, yt0, yt1);
    float Sg  = s0 + s1,   Yg  = y0 + y1;
    float Stg = st0 + st1, Ytg = yt0 + yt1;
    int o = bc * H + h;
    out[o]             = __fdividef(Yg, Sg);
    out[B*C*H + o]     = LN2 * (Mg + lg2(Sg));
    out[2*B*C*H + o]   = __fdividef(Ytg, Stg);
}

extern "C" void kernel_launch(void* const* d_in, const int* in_sizes, int n_in,
                              void* d_out, int out_size)
{
    const float* x_t  = (const float*)d_in[0];
    const float* d    = (const float*)d_in[1];
    const float* m    = (const float*)d_in[2];
    const float* kern = (const float*)d_in[3];
    float* out = (float*)d_out;

    interp_kernel<<<B * C, BDIM>>>(x_t, d, m, kern, out);
}